// round 13
// baseline (speedup 1.0000x reference)
#include <cuda_runtime.h>
#include <cstdint>
#include <cstddef>

#define B_ROWS 8192
#define KDIM   4096
#define KW     128              // 4096 bits / 32
#define NMAX   4096
#define RCHUNK 32
#define ROWS_PER_CHUNK (B_ROWS / RCHUNK)   // 256

#define TILE       128
#define SROW       129                      // padded row stride (words) in smem
#define SMEM_GEMM  (2 * TILE * SROW * 4)    // 132096 bytes

#define NCSA       16                       // 16 CSA groups of 7 words = 112
#define PLAIN0     (NCSA * 7)               // plain words 112..127 (8 pairs)

// ---------------- scratch (device globals; no runtime allocation) ----------------
__device__ unsigned   g_A0[(size_t)B_ROWS * KW];        // 4 MB  packed activations ping
__device__ unsigned   g_A1[(size_t)B_ROWS * KW];        // 4 MB  packed activations pong
__device__ unsigned   g_Wb[(size_t)NMAX * KW];          // 2 MB  packed weights (per layer)
__device__ short      g_S [(size_t)B_ROWS * NMAX];      // 67 MB pre-BN int16 activations
__device__ int        g_psum  [RCHUNK * NMAX];
__device__ long long  g_psumsq[RCHUNK * NMAX];
__device__ int        g_pmax  [RCHUNK * NMAX];
__device__ int        g_pmin  [RCHUNK * NMAX];
__device__ float      g_mu[NMAX];
__device__ float      g_scale[NMAX];
__device__ float      g_amax[NMAX];
__device__ float      g_pexp[RCHUNK * 1024];
__device__ float      g_dinv[1024];

template<int IMM>
__device__ __forceinline__ unsigned lop3(unsigned a, unsigned b, unsigned c) {
    unsigned r;
    asm("lop3.b32 %0, %1, %2, %3, %4;" : "=r"(r) : "r"(a), "r"(b), "r"(c), "n"(IMM));
    return r;
}

// ---------------- 1) binarize+pack x ----------------
__global__ void pack_x_kernel(const float* __restrict__ x) {
    unsigned idx = blockIdx.x * 256u + threadIdx.x;          // over B*K (exact)
    float v = x[idx];
    unsigned m = __ballot_sync(0xFFFFFFFFu, (v - 0.5f) >= 0.0f);
    if ((threadIdx.x & 31u) == 0u) g_A0[idx >> 5] = m;
}

// ---------------- 2) binarize+pack W, column-major bits: g_Wb[j][w] ----------------
__global__ void pack_w_kernel(const float* __restrict__ W, int N) {
    int j = blockIdx.x * 256 + threadIdx.x;                  // output column
    int w = blockIdx.y;                                      // k-word 0..127
    const float* p = W + (size_t)w * 32 * N + j;
    unsigned m = 0;
    #pragma unroll
    for (int b = 0; b < 32; ++b)
        if (p[(size_t)b * N] >= 0.0f) m |= (1u << b);
    g_Wb[(size_t)j * KW + w] = m;
}

// ---------------- 3) XNOR GEMM (R8 structure): 16 x 7:3-CSA groups + 8 plain pairs ----------------
// smem layout [word][row] (row stride 129 words); thread rows strided by 16 -> conflict-free LDS.
__global__ __launch_bounds__(256, 1)
void gemm_popc_kernel(int which_a, int N) {
    const unsigned* __restrict__ A = which_a ? g_A1 : g_A0;
    extern __shared__ unsigned sm[];
    unsigned* sA = sm;
    unsigned* sB = sm + TILE * SROW;

    int tid = threadIdx.x, wid = tid >> 5, lane = tid & 31;
    int tx = tid & 15, ty = tid >> 4;
    int rowBlk = blockIdx.y * TILE, colBlk = blockIdx.x * TILE;

    // one-shot load + transpose into [word][row]
    #pragma unroll
    for (int p = 0; p < 16; ++p) {
        int row = p * 8 + wid;
        uint4 va = *(const uint4*)(A    + (size_t)(rowBlk + row) * KW + lane * 4);
        uint4 vb = *(const uint4*)(g_Wb + (size_t)(colBlk + row) * KW + lane * 4);
        sA[(lane * 4 + 0) * SROW + row] = va.x;
        sA[(lane * 4 + 1) * SROW + row] = va.y;
        sA[(lane * 4 + 2) * SROW + row] = va.z;
        sA[(lane * 4 + 3) * SROW + row] = va.w;
        sB[(lane * 4 + 0) * SROW + row] = vb.x;
        sB[(lane * 4 + 1) * SROW + row] = vb.y;
        sB[(lane * 4 + 2) * SROW + row] = vb.z;
        sB[(lane * 4 + 3) * SROW + row] = vb.w;
    }
    __syncthreads();

    int acc[8][8];                                            // weighted mismatch counts
    #pragma unroll
    for (int m = 0; m < 8; ++m)
        #pragma unroll
        for (int n = 0; n < 8; ++n) acc[m][n] = 0;

    // ---- CSA part: 16 groups of 7 words (words 0..111) ----
    unsigned aF[8][7];
    for (int g = 0; g < NCSA; ++g) {
        int w0 = g * 7;
        #pragma unroll
        for (int mt = 0; mt < 8; ++mt)
            #pragma unroll
            for (int i = 0; i < 7; ++i)
                aF[mt][i] = sA[(w0 + i) * SROW + ty + 16 * mt];
        #pragma unroll
        for (int nt = 0; nt < 8; ++nt) {
            unsigned b[7];
            #pragma unroll
            for (int i = 0; i < 7; ++i)
                b[i] = sB[(w0 + i) * SROW + tx + 16 * nt];
            #pragma unroll
            for (int mt = 0; mt < 8; ++mt) {
                unsigned x0 = aF[mt][0] ^ b[0], x1 = aF[mt][1] ^ b[1];
                unsigned x2 = aF[mt][2] ^ b[2], x3 = aF[mt][3] ^ b[3];
                unsigned x4 = aF[mt][4] ^ b[4], x5 = aF[mt][5] ^ b[5];
                unsigned x6 = aF[mt][6] ^ b[6];
                unsigned s0 = lop3<0x96>(x0, x1, x2), c0 = lop3<0xE8>(x0, x1, x2);
                unsigned s1 = lop3<0x96>(x3, x4, x5), c1 = lop3<0xE8>(x3, x4, x5);
                unsigned s2 = lop3<0x96>(s0, s1, x6), c2 = lop3<0xE8>(s0, s1, x6);
                unsigned s3 = lop3<0x96>(c0, c1, c2), c3 = lop3<0xE8>(c0, c1, c2);
                acc[mt][nt] += __popc(s2) + 2 * __popc(s3) + 4 * __popc(c3);
            }
        }
    }

    // ---- plain part: words 112..127 as 8 pairs (same shape as R8's leftover block) ----
    #pragma unroll
    for (int pr = 0; pr < 8; ++pr) {
        int w0 = PLAIN0 + pr * 2;
        unsigned aL[8][2];
        #pragma unroll
        for (int mt = 0; mt < 8; ++mt) {
            aL[mt][0] = sA[(w0 + 0) * SROW + ty + 16 * mt];
            aL[mt][1] = sA[(w0 + 1) * SROW + ty + 16 * mt];
        }
        #pragma unroll
        for (int nt = 0; nt < 8; ++nt) {
            unsigned b0 = sB[(w0 + 0) * SROW + tx + 16 * nt];
            unsigned b1 = sB[(w0 + 1) * SROW + tx + 16 * nt];
            #pragma unroll
            for (int mt = 0; mt < 8; ++mt)
                acc[mt][nt] += __popc(aL[mt][0] ^ b0) + __popc(aL[mt][1] ^ b1);
        }
    }

    #pragma unroll
    for (int mt = 0; mt < 8; ++mt) {
        int row = rowBlk + ty + 16 * mt;
        #pragma unroll
        for (int nt = 0; nt < 8; ++nt) {
            int col = colBlk + tx + 16 * nt;
            g_S[(size_t)row * N + col] = (short)(KDIM - 2 * acc[mt][nt]);
        }
    }
}

// ---------------- 4) per-column partial stats (int16 source, scalar) ----------------
__global__ void colstats_kernel(int N) {
    int j = blockIdx.x * 256 + threadIdx.x;
    int c = blockIdx.y;
    const short* p = g_S + (size_t)c * ROWS_PER_CHUNK * N + j;
    int sum = 0;
    long long ss = 0;
    int mx = -2147483647, mn = 2147483647;
    #pragma unroll 8
    for (int r = 0; r < ROWS_PER_CHUNK; ++r) {
        int v = p[(size_t)r * N];
        sum += v; ss += v * v;
        mx = max(mx, v); mn = min(mn, v);
    }
    g_psum[c * N + j] = sum; g_psumsq[c * N + j] = ss;
    g_pmax[c * N + j] = mx;  g_pmin[c * N + j] = mn;
}

// ---------------- 5) finalize mu/scale/amax ----------------
__global__ void finalize_stats_kernel(const float* __restrict__ gamma,
                                      const float* __restrict__ beta,
                                      int layer, int N) {
    int j = blockIdx.x * 256 + threadIdx.x;
    long long sum = 0, ss = 0;
    int mx = -2147483647, mn = 2147483647;
    #pragma unroll
    for (int c = 0; c < RCHUNK; ++c) {
        sum += g_psum[c * N + j]; ss += g_psumsq[c * N + j];
        mx = max(mx, g_pmax[c * N + j]); mn = min(mn, g_pmin[c * N + j]);
    }
    double m   = (double)sum / (double)B_ROWS;
    double var = (double)ss  / (double)B_ROWS - m * m;
    float sc = gamma[layer] * rsqrtf((float)var + 1e-5f);
    float be = beta[layer];
    g_mu[j] = (float)m; g_scale[j] = sc;
    float hi = ((float)mx - (float)m) * sc + be;
    float lo = ((float)mn - (float)m) * sc + be;
    g_amax[j] = fmaxf(hi, lo);
}

// ---------------- 6) BN + binarize + repack ----------------
__global__ void bn_bin_pack_kernel(const float* __restrict__ beta,
                                   int layer, int which_out, int N) {
    unsigned idx = blockIdx.x * 256u + threadIdx.x;          // over B*N (exact)
    int j = idx & (unsigned)(N - 1);
    float a = ((float)g_S[idx] - g_mu[j]) * g_scale[j] + beta[layer];
    unsigned m = __ballot_sync(0xFFFFFFFFu, a >= 0.0f);
    unsigned* out = which_out ? g_A1 : g_A0;
    if ((threadIdx.x & 31u) == 0u) out[idx >> 5] = m;
}

// ---------------- 7) softmax over batch ----------------
__global__ void sumexp_kernel(const float* __restrict__ beta, int N) {
    int j = blockIdx.x * 256 + threadIdx.x;
    int c = blockIdx.y;
    float m = g_mu[j], sc = g_scale[j], be = beta[2], ax = g_amax[j];
    const short* p = g_S + (size_t)c * ROWS_PER_CHUNK * N + j;
    float sum = 0.0f;
    #pragma unroll 8
    for (int r = 0; r < ROWS_PER_CHUNK; ++r)
        sum += __expf(((float)p[(size_t)r * N] - m) * sc + be - ax);
    g_pexp[c * N + j] = sum;
}
__global__ void finalize_denom_kernel(int N) {
    int j = blockIdx.x * 256 + threadIdx.x;
    float s = 0.0f;
    #pragma unroll
    for (int c = 0; c < RCHUNK; ++c) s += g_pexp[c * N + j];
    g_dinv[j] = 1.0f / s;
}
__global__ void write_out_kernel(const float* __restrict__ beta,
                                 float* __restrict__ out, int N) {
    unsigned idx = blockIdx.x * 256u + threadIdx.x;
    int j = idx & (unsigned)(N - 1);
    float a = ((float)g_S[idx] - g_mu[j]) * g_scale[j] + beta[2] - g_amax[j];
    out[idx] = __expf(a) * g_dinv[j];
}

// ---------------- driver ----------------
extern "C" void kernel_launch(void* const* d_in, const int* in_sizes, int n_in,
                              void* d_out, int out_size) {
    (void)in_sizes; (void)n_in; (void)out_size;
    const float* x     = (const float*)d_in[0];
    const float* Ws[3] = {(const float*)d_in[1], (const float*)d_in[2], (const float*)d_in[3]};
    const float* gamma = (const float*)d_in[4];
    const float* beta  = (const float*)d_in[5];
    float* out = (float*)d_out;
    const int Ns[3] = {4096, 4096, 1024};

    cudaFuncSetAttribute(gemm_popc_kernel, cudaFuncAttributeMaxDynamicSharedMemorySize, SMEM_GEMM);

    pack_x_kernel<<<(B_ROWS * KDIM) / 256, 256>>>(x);

    int cur = 0;
    for (int k = 0; k < 3; ++k) {
        int N = Ns[k];
        pack_w_kernel<<<dim3(N / 256, KW), 256>>>(Ws[k], N);
        gemm_popc_kernel<<<dim3(N / TILE, B_ROWS / TILE), 256, SMEM_GEMM>>>(cur, N);
        colstats_kernel<<<dim3(N / 256, RCHUNK), 256>>>(N);
        finalize_stats_kernel<<<N / 256, 256>>>(gamma, beta, k, N);
        if (k < 2) {
            bn_bin_pack_kernel<<<(B_ROWS * N) / 256, 256>>>(beta, k, cur ^ 1, N);
            cur ^= 1;
        } else {
            sumexp_kernel<<<dim3(N / 256, RCHUNK), 256>>>(beta, N);
            finalize_denom_kernel<<<N / 256, 256>>>(N);
            write_out_kernel<<<(B_ROWS * N) / 256, 256>>>(beta, out, N);
        }
    }
}

// round 14
// speedup vs baseline: 1.0230x; 1.0230x over previous
#include <cuda_runtime.h>
#include <cstdint>
#include <cstddef>

#define B_ROWS 8192
#define KDIM   4096
#define KW     128              // 4096 bits / 32
#define NMAX   4096
#define RCHUNK 32
#define ROWS_PER_CHUNK (B_ROWS / RCHUNK)   // 256

#define TILE       128
#define SROW       129                      // padded row stride (words) in smem
#define SMEM_GEMM  (2 * TILE * SROW * 4)    // 132096 bytes

#define N15        8                        // 8 groups of 15 words = 120
#define W73        120                      // one 7:3 group: words 120..126
#define WPL        127                      // plain word 127

// ---------------- scratch (device globals; no runtime allocation) ----------------
__device__ unsigned   g_A0[(size_t)B_ROWS * KW];        // 4 MB  packed activations ping
__device__ unsigned   g_A1[(size_t)B_ROWS * KW];        // 4 MB  packed activations pong
__device__ unsigned   g_Wb[(size_t)NMAX * KW];          // 2 MB  packed weights (per layer)
__device__ short      g_S [(size_t)B_ROWS * NMAX];      // 67 MB pre-BN int16 activations
__device__ int        g_psum  [RCHUNK * NMAX];
__device__ long long  g_psumsq[RCHUNK * NMAX];
__device__ int        g_pmax  [RCHUNK * NMAX];
__device__ int        g_pmin  [RCHUNK * NMAX];
__device__ float      g_mu[NMAX];
__device__ float      g_scale[NMAX];
__device__ float      g_amax[NMAX];
__device__ float      g_pexp[RCHUNK * 1024];
__device__ float      g_dinv[1024];

template<int IMM>
__device__ __forceinline__ unsigned lop3(unsigned a, unsigned b, unsigned c) {
    unsigned r;
    asm("lop3.b32 %0, %1, %2, %3, %4;" : "=r"(r) : "r"(a), "r"(b), "r"(c), "n"(IMM));
    return r;
}
#define FA(s, c, x, y, z) { s = lop3<0x96>(x, y, z); c = lop3<0xE8>(x, y, z); }

// ---------------- 1) binarize+pack x ----------------
__global__ void pack_x_kernel(const float* __restrict__ x) {
    unsigned idx = blockIdx.x * 256u + threadIdx.x;          // over B*K (exact)
    float v = x[idx];
    unsigned m = __ballot_sync(0xFFFFFFFFu, (v - 0.5f) >= 0.0f);
    if ((threadIdx.x & 31u) == 0u) g_A0[idx >> 5] = m;
}

// ---------------- 2) binarize+pack W, column-major bits: g_Wb[j][w] ----------------
__global__ void pack_w_kernel(const float* __restrict__ W, int N) {
    int j = blockIdx.x * 256 + threadIdx.x;                  // output column
    int w = blockIdx.y;                                      // k-word 0..127
    const float* p = W + (size_t)w * 32 * N + j;
    unsigned m = 0;
    #pragma unroll
    for (int b = 0; b < 32; ++b)
        if (p[(size_t)b * N] >= 0.0f) m |= (1u << b);
    g_Wb[(size_t)j * KW + w] = m;
}

// ---------------- 3) XNOR GEMM: 8 x 15:4 counters + 1 x 7:3 + 1 plain ----------------
// smem layout [word][row] (row stride 129 words); thread rows strided by 16 -> conflict-free LDS.
__global__ __launch_bounds__(256, 1)
void gemm_popc_kernel(int which_a, int N) {
    const unsigned* __restrict__ A = which_a ? g_A1 : g_A0;
    extern __shared__ unsigned sm[];
    unsigned* sA = sm;
    unsigned* sB = sm + TILE * SROW;

    int tid = threadIdx.x, wid = tid >> 5, lane = tid & 31;
    int tx = tid & 15, ty = tid >> 4;
    int rowBlk = blockIdx.y * TILE, colBlk = blockIdx.x * TILE;

    // one-shot load + transpose into [word][row]
    #pragma unroll
    for (int p = 0; p < 16; ++p) {
        int row = p * 8 + wid;
        uint4 va = *(const uint4*)(A    + (size_t)(rowBlk + row) * KW + lane * 4);
        uint4 vb = *(const uint4*)(g_Wb + (size_t)(colBlk + row) * KW + lane * 4);
        sA[(lane * 4 + 0) * SROW + row] = va.x;
        sA[(lane * 4 + 1) * SROW + row] = va.y;
        sA[(lane * 4 + 2) * SROW + row] = va.z;
        sA[(lane * 4 + 3) * SROW + row] = va.w;
        sB[(lane * 4 + 0) * SROW + row] = vb.x;
        sB[(lane * 4 + 1) * SROW + row] = vb.y;
        sB[(lane * 4 + 2) * SROW + row] = vb.z;
        sB[(lane * 4 + 3) * SROW + row] = vb.w;
    }
    __syncthreads();

    int acc[8][8];                                            // weighted mismatch counts
    #pragma unroll
    for (int m = 0; m < 8; ++m)
        #pragma unroll
        for (int n = 0; n < 8; ++n) acc[m][n] = 0;

    // ---- 15:4 part: 8 groups of 15 words (words 0..119) ----
    unsigned aF[8][15];
    for (int g = 0; g < N15; ++g) {
        int w0 = g * 15;
        #pragma unroll
        for (int mt = 0; mt < 8; ++mt)
            #pragma unroll
            for (int i = 0; i < 15; ++i)
                aF[mt][i] = sA[(w0 + i) * SROW + ty + 16 * mt];
        #pragma unroll
        for (int nt = 0; nt < 8; ++nt) {
            unsigned b[15];
            #pragma unroll
            for (int i = 0; i < 15; ++i)
                b[i] = sB[(w0 + i) * SROW + tx + 16 * nt];
            #pragma unroll
            for (int mt = 0; mt < 8; ++mt) {
                // layer 1: five FAs over xors
                unsigned s0, c0, s1, c1, s2, c2, s3, c3, s4, c4;
                FA(s0, c0, aF[mt][0] ^ b[0],  aF[mt][1] ^ b[1],  aF[mt][2] ^ b[2]);
                FA(s1, c1, aF[mt][3] ^ b[3],  aF[mt][4] ^ b[4],  aF[mt][5] ^ b[5]);
                FA(s2, c2, aF[mt][6] ^ b[6],  aF[mt][7] ^ b[7],  aF[mt][8] ^ b[8]);
                FA(s3, c3, aF[mt][9] ^ b[9],  aF[mt][10] ^ b[10], aF[mt][11] ^ b[11]);
                FA(s4, c4, aF[mt][12] ^ b[12], aF[mt][13] ^ b[13], aF[mt][14] ^ b[14]);
                // weight-1 reduction
                unsigned s5, c5, S1, c6;
                FA(s5, c5, s0, s1, s2);
                FA(S1, c6, s3, s4, s5);
                // weight-2 reduction (c0..c5, c6)
                unsigned s6, c7, s7, c8, S2, c9;
                FA(s6, c7, c0, c1, c2);
                FA(s7, c8, c3, c4, c5);
                FA(S2, c9, s6, s7, c6);
                // weight-4 reduction
                unsigned S4, S8;
                FA(S4, S8, c7, c8, c9);
                acc[mt][nt] += __popc(S1) + 2 * __popc(S2) + 4 * __popc(S4) + 8 * __popc(S8);
            }
        }
    }

    // ---- 7:3 group: words 120..126 ----
    {
        unsigned aG[8][7];
        #pragma unroll
        for (int mt = 0; mt < 8; ++mt)
            #pragma unroll
            for (int i = 0; i < 7; ++i)
                aG[mt][i] = sA[(W73 + i) * SROW + ty + 16 * mt];
        #pragma unroll
        for (int nt = 0; nt < 8; ++nt) {
            unsigned b[7];
            #pragma unroll
            for (int i = 0; i < 7; ++i)
                b[i] = sB[(W73 + i) * SROW + tx + 16 * nt];
            #pragma unroll
            for (int mt = 0; mt < 8; ++mt) {
                unsigned s0, c0, s1, c1, s2, c2, s3, c3;
                FA(s0, c0, aG[mt][0] ^ b[0], aG[mt][1] ^ b[1], aG[mt][2] ^ b[2]);
                FA(s1, c1, aG[mt][3] ^ b[3], aG[mt][4] ^ b[4], aG[mt][5] ^ b[5]);
                FA(s2, c2, s0, s1, aG[mt][6] ^ b[6]);
                FA(s3, c3, c0, c1, c2);
                acc[mt][nt] += __popc(s2) + 2 * __popc(s3) + 4 * __popc(c3);
            }
        }
    }

    // ---- plain word 127 ----
    {
        unsigned aL[8];
        #pragma unroll
        for (int mt = 0; mt < 8; ++mt)
            aL[mt] = sA[WPL * SROW + ty + 16 * mt];
        #pragma unroll
        for (int nt = 0; nt < 8; ++nt) {
            unsigned b0 = sB[WPL * SROW + tx + 16 * nt];
            #pragma unroll
            for (int mt = 0; mt < 8; ++mt)
                acc[mt][nt] += __popc(aL[mt] ^ b0);
        }
    }

    #pragma unroll
    for (int mt = 0; mt < 8; ++mt) {
        int row = rowBlk + ty + 16 * mt;
        #pragma unroll
        for (int nt = 0; nt < 8; ++nt) {
            int col = colBlk + tx + 16 * nt;
            g_S[(size_t)row * N + col] = (short)(KDIM - 2 * acc[mt][nt]);
        }
    }
}

// ---------------- 4) per-column partial stats (int16 source, scalar) ----------------
__global__ void colstats_kernel(int N) {
    int j = blockIdx.x * 256 + threadIdx.x;
    int c = blockIdx.y;
    const short* p = g_S + (size_t)c * ROWS_PER_CHUNK * N + j;
    int sum = 0;
    long long ss = 0;
    int mx = -2147483647, mn = 2147483647;
    #pragma unroll 8
    for (int r = 0; r < ROWS_PER_CHUNK; ++r) {
        int v = p[(size_t)r * N];
        sum += v; ss += v * v;
        mx = max(mx, v); mn = min(mn, v);
    }
    g_psum[c * N + j] = sum; g_psumsq[c * N + j] = ss;
    g_pmax[c * N + j] = mx;  g_pmin[c * N + j] = mn;
}

// ---------------- 5) finalize mu/scale/amax ----------------
__global__ void finalize_stats_kernel(const float* __restrict__ gamma,
                                      const float* __restrict__ beta,
                                      int layer, int N) {
    int j = blockIdx.x * 256 + threadIdx.x;
    long long sum = 0, ss = 0;
    int mx = -2147483647, mn = 2147483647;
    #pragma unroll
    for (int c = 0; c < RCHUNK; ++c) {
        sum += g_psum[c * N + j]; ss += g_psumsq[c * N + j];
        mx = max(mx, g_pmax[c * N + j]); mn = min(mn, g_pmin[c * N + j]);
    }
    double m   = (double)sum / (double)B_ROWS;
    double var = (double)ss  / (double)B_ROWS - m * m;
    float sc = gamma[layer] * rsqrtf((float)var + 1e-5f);
    float be = beta[layer];
    g_mu[j] = (float)m; g_scale[j] = sc;
    float hi = ((float)mx - (float)m) * sc + be;
    float lo = ((float)mn - (float)m) * sc + be;
    g_amax[j] = fmaxf(hi, lo);
}

// ---------------- 6) BN + binarize + repack ----------------
__global__ void bn_bin_pack_kernel(const float* __restrict__ beta,
                                   int layer, int which_out, int N) {
    unsigned idx = blockIdx.x * 256u + threadIdx.x;          // over B*N (exact)
    int j = idx & (unsigned)(N - 1);
    float a = ((float)g_S[idx] - g_mu[j]) * g_scale[j] + beta[layer];
    unsigned m = __ballot_sync(0xFFFFFFFFu, a >= 0.0f);
    unsigned* out = which_out ? g_A1 : g_A0;
    if ((threadIdx.x & 31u) == 0u) out[idx >> 5] = m;
}

// ---------------- 7) softmax over batch ----------------
__global__ void sumexp_kernel(const float* __restrict__ beta, int N) {
    int j = blockIdx.x * 256 + threadIdx.x;
    int c = blockIdx.y;
    float m = g_mu[j], sc = g_scale[j], be = beta[2], ax = g_amax[j];
    const short* p = g_S + (size_t)c * ROWS_PER_CHUNK * N + j;
    float sum = 0.0f;
    #pragma unroll 8
    for (int r = 0; r < ROWS_PER_CHUNK; ++r)
        sum += __expf(((float)p[(size_t)r * N] - m) * sc + be - ax);
    g_pexp[c * N + j] = sum;
}
__global__ void finalize_denom_kernel(int N) {
    int j = blockIdx.x * 256 + threadIdx.x;
    float s = 0.0f;
    #pragma unroll
    for (int c = 0; c < RCHUNK; ++c) s += g_pexp[c * N + j];
    g_dinv[j] = 1.0f / s;
}
__global__ void write_out_kernel(const float* __restrict__ beta,
                                 float* __restrict__ out, int N) {
    unsigned idx = blockIdx.x * 256u + threadIdx.x;
    int j = idx & (unsigned)(N - 1);
    float a = ((float)g_S[idx] - g_mu[j]) * g_scale[j] + beta[2] - g_amax[j];
    out[idx] = __expf(a) * g_dinv[j];
}

// ---------------- driver ----------------
extern "C" void kernel_launch(void* const* d_in, const int* in_sizes, int n_in,
                              void* d_out, int out_size) {
    (void)in_sizes; (void)n_in; (void)out_size;
    const float* x     = (const float*)d_in[0];
    const float* Ws[3] = {(const float*)d_in[1], (const float*)d_in[2], (const float*)d_in[3]};
    const float* gamma = (const float*)d_in[4];
    const float* beta  = (const float*)d_in[5];
    float* out = (float*)d_out;
    const int Ns[3] = {4096, 4096, 1024};

    cudaFuncSetAttribute(gemm_popc_kernel, cudaFuncAttributeMaxDynamicSharedMemorySize, SMEM_GEMM);

    pack_x_kernel<<<(B_ROWS * KDIM) / 256, 256>>>(x);

    int cur = 0;
    for (int k = 0; k < 3; ++k) {
        int N = Ns[k];
        pack_w_kernel<<<dim3(N / 256, KW), 256>>>(Ws[k], N);
        gemm_popc_kernel<<<dim3(N / TILE, B_ROWS / TILE), 256, SMEM_GEMM>>>(cur, N);
        colstats_kernel<<<dim3(N / 256, RCHUNK), 256>>>(N);
        finalize_stats_kernel<<<N / 256, 256>>>(gamma, beta, k, N);
        if (k < 2) {
            bn_bin_pack_kernel<<<(B_ROWS * N) / 256, 256>>>(beta, k, cur ^ 1, N);
            cur ^= 1;
        } else {
            sumexp_kernel<<<dim3(N / 256, RCHUNK), 256>>>(beta, N);
            finalize_denom_kernel<<<N / 256, 256>>>(N);
            write_out_kernel<<<(B_ROWS * N) / 256, 256>>>(beta, out, N);
        }
    }
}

// round 15
// speedup vs baseline: 1.1040x; 1.0792x over previous
#include <cuda_runtime.h>
#include <cstdint>
#include <cstddef>

#define B_ROWS 8192
#define KDIM   4096
#define KW     128              // 4096 bits / 32
#define NMAX   4096
#define SCHUNK 64               // stat chunks = gemm grid.y (8192/128)
#define ECHUNK 32               // sumexp row chunks
#define EROWS  (B_ROWS / ECHUNK)            // 256

#define TILE       128
#define SROW       129                      // padded row stride (words) in smem
#define SMEM_GEMM  (2 * TILE * SROW * 4)    // 132096 bytes

// ---------------- scratch (device globals; no runtime allocation) ----------------
__device__ unsigned   g_A0[(size_t)B_ROWS * KW];        // 4 MB  packed activations ping
__device__ unsigned   g_A1[(size_t)B_ROWS * KW];        // 4 MB  packed activations pong
__device__ unsigned   g_Wb[(size_t)NMAX * KW];          // 2 MB  packed weights (per layer)
__device__ short      g_S [(size_t)B_ROWS * NMAX];      // 67 MB pre-BN int16 activations
__device__ int        g_psum  [SCHUNK * NMAX];
__device__ long long  g_psumsq[SCHUNK * NMAX];
__device__ int        g_pmax  [SCHUNK * NMAX];
__device__ int        g_pmin  [SCHUNK * NMAX];
__device__ float      g_mu[NMAX];
__device__ float      g_scale[NMAX];
__device__ float      g_amax[NMAX];
__device__ float      g_pexp[ECHUNK * 1024];
__device__ float      g_dinv[1024];

template<int IMM>
__device__ __forceinline__ unsigned lop3(unsigned a, unsigned b, unsigned c) {
    unsigned r;
    asm("lop3.b32 %0, %1, %2, %3, %4;" : "=r"(r) : "r"(a), "r"(b), "r"(c), "n"(IMM));
    return r;
}

// ---------------- 1) binarize+pack x ----------------
__global__ void pack_x_kernel(const float* __restrict__ x) {
    unsigned idx = blockIdx.x * 256u + threadIdx.x;          // over B*K (exact)
    float v = x[idx];
    unsigned m = __ballot_sync(0xFFFFFFFFu, (v - 0.5f) >= 0.0f);
    if ((threadIdx.x & 31u) == 0u) g_A0[idx >> 5] = m;
}

// ---------------- 2) binarize+pack W, column-major bits: g_Wb[j][w] ----------------
__global__ void pack_w_kernel(const float* __restrict__ W, int N) {
    int j = blockIdx.x * 256 + threadIdx.x;                  // output column
    int w = blockIdx.y;                                      // k-word 0..127
    const float* p = W + (size_t)w * 32 * N + j;
    unsigned m = 0;
    #pragma unroll
    for (int b = 0; b < 32; ++b)
        if (p[(size_t)b * N] >= 0.0f) m |= (1u << b);
    g_Wb[(size_t)j * KW + w] = m;
}

// ---------------- 3) XNOR GEMM (R8 mainloop) + fused column-stats epilogue ----------------
// smem layout [word][row] (row stride 129 words); thread rows strided by 16 -> conflict-free LDS.
__global__ __launch_bounds__(256, 1)
void gemm_popc_kernel(int which_a, int N) {
    const unsigned* __restrict__ A = which_a ? g_A1 : g_A0;
    extern __shared__ unsigned sm[];
    unsigned* sA = sm;
    unsigned* sB = sm + TILE * SROW;

    int tid = threadIdx.x, wid = tid >> 5, lane = tid & 31;
    int tx = tid & 15, ty = tid >> 4;
    int rowBlk = blockIdx.y * TILE, colBlk = blockIdx.x * TILE;

    // one-shot load + transpose into [word][row]
    #pragma unroll
    for (int p = 0; p < 16; ++p) {
        int row = p * 8 + wid;
        uint4 va = *(const uint4*)(A    + (size_t)(rowBlk + row) * KW + lane * 4);
        uint4 vb = *(const uint4*)(g_Wb + (size_t)(colBlk + row) * KW + lane * 4);
        sA[(lane * 4 + 0) * SROW + row] = va.x;
        sA[(lane * 4 + 1) * SROW + row] = va.y;
        sA[(lane * 4 + 2) * SROW + row] = va.z;
        sA[(lane * 4 + 3) * SROW + row] = va.w;
        sB[(lane * 4 + 0) * SROW + row] = vb.x;
        sB[(lane * 4 + 1) * SROW + row] = vb.y;
        sB[(lane * 4 + 2) * SROW + row] = vb.z;
        sB[(lane * 4 + 3) * SROW + row] = vb.w;
    }
    __syncthreads();

    int acc[8][8];                                            // weighted mismatch counts
    #pragma unroll
    for (int m = 0; m < 8; ++m)
        #pragma unroll
        for (int n = 0; n < 8; ++n) acc[m][n] = 0;

    unsigned aF[8][7];
    for (int g = 0; g < 18; ++g) {                            // 18 groups of 7 words
        int w0 = g * 7;
        #pragma unroll
        for (int mt = 0; mt < 8; ++mt)
            #pragma unroll
            for (int i = 0; i < 7; ++i)
                aF[mt][i] = sA[(w0 + i) * SROW + ty + 16 * mt];
        #pragma unroll
        for (int nt = 0; nt < 8; ++nt) {
            unsigned b[7];
            #pragma unroll
            for (int i = 0; i < 7; ++i)
                b[i] = sB[(w0 + i) * SROW + tx + 16 * nt];
            #pragma unroll
            for (int mt = 0; mt < 8; ++mt) {
                unsigned x0 = aF[mt][0] ^ b[0], x1 = aF[mt][1] ^ b[1];
                unsigned x2 = aF[mt][2] ^ b[2], x3 = aF[mt][3] ^ b[3];
                unsigned x4 = aF[mt][4] ^ b[4], x5 = aF[mt][5] ^ b[5];
                unsigned x6 = aF[mt][6] ^ b[6];
                unsigned s0 = lop3<0x96>(x0, x1, x2), c0 = lop3<0xE8>(x0, x1, x2);
                unsigned s1 = lop3<0x96>(x3, x4, x5), c1 = lop3<0xE8>(x3, x4, x5);
                unsigned s2 = lop3<0x96>(s0, s1, x6), c2 = lop3<0xE8>(s0, s1, x6);
                unsigned s3 = lop3<0x96>(c0, c1, c2), c3 = lop3<0xE8>(c0, c1, c2);
                acc[mt][nt] += __popc(s2) + 2 * __popc(s3) + 4 * __popc(c3);
            }
        }
    }
    // leftover words 126, 127 (weight-1 direct popcounts)
    {
        unsigned aL[8][2];
        #pragma unroll
        for (int mt = 0; mt < 8; ++mt) {
            aL[mt][0] = sA[126 * SROW + ty + 16 * mt];
            aL[mt][1] = sA[127 * SROW + ty + 16 * mt];
        }
        #pragma unroll
        for (int nt = 0; nt < 8; ++nt) {
            unsigned b0 = sB[126 * SROW + tx + 16 * nt];
            unsigned b1 = sB[127 * SROW + tx + 16 * nt];
            #pragma unroll
            for (int mt = 0; mt < 8; ++mt)
                acc[mt][nt] += __popc(aL[mt][0] ^ b0) + __popc(aL[mt][1] ^ b1);
        }
    }

    // ---- store S tile + per-thread column partials (8 cols, 8 rows each) ----
    int psum[8], pss[8], pmx[8], pmn[8];
    #pragma unroll
    for (int nt = 0; nt < 8; ++nt) { psum[nt] = 0; pss[nt] = 0; pmx[nt] = -2147483647; pmn[nt] = 2147483647; }
    #pragma unroll
    for (int mt = 0; mt < 8; ++mt) {
        int row = rowBlk + ty + 16 * mt;
        #pragma unroll
        for (int nt = 0; nt < 8; ++nt) {
            int v = KDIM - 2 * acc[mt][nt];
            int col = colBlk + tx + 16 * nt;
            g_S[(size_t)row * N + col] = (short)v;
            psum[nt] += v;
            pss[nt]  += v * v;                               // <= 8*4096^2 < 2^31
            pmx[nt] = max(pmx[nt], v);
            pmn[nt] = min(pmn[nt], v);
        }
    }

    // ---- smem reduce over ty (16 partials per column), then direct writes ----
    __syncthreads();                                          // done reading sA/sB
    int* rs = (int*)sm;                                       // 4 arrays of [8][16][16]
    int* rq = rs + 2048;
    int* rx = rq + 2048;
    int* rn = rx + 2048;
    #pragma unroll
    for (int nt = 0; nt < 8; ++nt) {
        int o = nt * 256 + ty * 16 + tx;
        rs[o] = psum[nt]; rq[o] = pss[nt]; rx[o] = pmx[nt]; rn[o] = pmn[nt];
    }
    __syncthreads();
    if (tid < 128) {                                          // one thread per column
        int nt = tid >> 4, cx = tid & 15;
        int sum = 0, mx = -2147483647, mn = 2147483647;
        long long ss = 0;
        #pragma unroll
        for (int t = 0; t < 16; ++t) {
            int o = nt * 256 + t * 16 + cx;
            sum += rs[o]; ss += (long long)rq[o];
            mx = max(mx, rx[o]); mn = min(mn, rn[o]);
        }
        int col = colBlk + cx + 16 * nt;
        int c = blockIdx.y;                                   // chunk = 128-row band
        g_psum  [c * N + col] = sum;
        g_psumsq[c * N + col] = ss;
        g_pmax  [c * N + col] = mx;
        g_pmin  [c * N + col] = mn;
    }
}

// ---------------- 5) finalize mu/scale/amax ----------------
__global__ void finalize_stats_kernel(const float* __restrict__ gamma,
                                      const float* __restrict__ beta,
                                      int layer, int N) {
    int j = blockIdx.x * 256 + threadIdx.x;
    long long sum = 0, ss = 0;
    int mx = -2147483647, mn = 2147483647;
    #pragma unroll 8
    for (int c = 0; c < SCHUNK; ++c) {
        sum += g_psum[c * N + j]; ss += g_psumsq[c * N + j];
        mx = max(mx, g_pmax[c * N + j]); mn = min(mn, g_pmin[c * N + j]);
    }
    double m   = (double)sum / (double)B_ROWS;
    double var = (double)ss  / (double)B_ROWS - m * m;
    float sc = gamma[layer] * rsqrtf((float)var + 1e-5f);
    float be = beta[layer];
    g_mu[j] = (float)m; g_scale[j] = sc;
    float hi = ((float)mx - (float)m) * sc + be;
    float lo = ((float)mn - (float)m) * sc + be;
    g_amax[j] = fmaxf(hi, lo);
}

// ---------------- 6) BN + binarize + repack ----------------
__global__ void bn_bin_pack_kernel(const float* __restrict__ beta,
                                   int layer, int which_out, int N) {
    unsigned idx = blockIdx.x * 256u + threadIdx.x;          // over B*N (exact)
    int j = idx & (unsigned)(N - 1);
    float a = ((float)g_S[idx] - g_mu[j]) * g_scale[j] + beta[layer];
    unsigned m = __ballot_sync(0xFFFFFFFFu, a >= 0.0f);
    unsigned* out = which_out ? g_A1 : g_A0;
    if ((threadIdx.x & 31u) == 0u) out[idx >> 5] = m;
}

// ---------------- 7) softmax over batch ----------------
__global__ void sumexp_kernel(const float* __restrict__ beta, int N) {
    int j = blockIdx.x * 256 + threadIdx.x;
    int c = blockIdx.y;
    float m = g_mu[j], sc = g_scale[j], be = beta[2], ax = g_amax[j];
    const short* p = g_S + (size_t)c * EROWS * N + j;
    float sum = 0.0f;
    #pragma unroll 8
    for (int r = 0; r < EROWS; ++r)
        sum += __expf(((float)p[(size_t)r * N] - m) * sc + be - ax);
    g_pexp[c * N + j] = sum;
}
__global__ void finalize_denom_kernel(int N) {
    int j = blockIdx.x * 256 + threadIdx.x;
    float s = 0.0f;
    #pragma unroll
    for (int c = 0; c < ECHUNK; ++c) s += g_pexp[c * N + j];
    g_dinv[j] = 1.0f / s;
}
__global__ void write_out_kernel(const float* __restrict__ beta,
                                 float* __restrict__ out, int N) {
    unsigned idx = blockIdx.x * 256u + threadIdx.x;
    int j = idx & (unsigned)(N - 1);
    float a = ((float)g_S[idx] - g_mu[j]) * g_scale[j] + beta[2] - g_amax[j];
    out[idx] = __expf(a) * g_dinv[j];
}

// ---------------- driver ----------------
extern "C" void kernel_launch(void* const* d_in, const int* in_sizes, int n_in,
                              void* d_out, int out_size) {
    (void)in_sizes; (void)n_in; (void)out_size;
    const float* x     = (const float*)d_in[0];
    const float* Ws[3] = {(const float*)d_in[1], (const float*)d_in[2], (const float*)d_in[3]};
    const float* gamma = (const float*)d_in[4];
    const float* beta  = (const float*)d_in[5];
    float* out = (float*)d_out;
    const int Ns[3] = {4096, 4096, 1024};

    cudaFuncSetAttribute(gemm_popc_kernel, cudaFuncAttributeMaxDynamicSharedMemorySize, SMEM_GEMM);

    pack_x_kernel<<<(B_ROWS * KDIM) / 256, 256>>>(x);

    int cur = 0;
    for (int k = 0; k < 3; ++k) {
        int N = Ns[k];
        pack_w_kernel<<<dim3(N / 256, KW), 256>>>(Ws[k], N);
        gemm_popc_kernel<<<dim3(N / TILE, B_ROWS / TILE), 256, SMEM_GEMM>>>(cur, N);
        finalize_stats_kernel<<<N / 256, 256>>>(gamma, beta, k, N);
        if (k < 2) {
            bn_bin_pack_kernel<<<(B_ROWS * N) / 256, 256>>>(beta, k, cur ^ 1, N);
            cur ^= 1;
        } else {
            sumexp_kernel<<<dim3(N / 256, ECHUNK), 256>>>(beta, N);
            finalize_denom_kernel<<<N / 256, 256>>>(N);
            write_out_kernel<<<(B_ROWS * N) / 256, 256>>>(beta, out, N);
        }
    }
}